// round 2
// baseline (speedup 1.0000x reference)
#include <cuda_runtime.h>

// Problem constants
#define B_TOT   4096
#define E_DIM   128
#define F_DIM   64
#define W_DIM   126      // E - 2
#define NBLK    444      // 3 * 148 SMs -> single wave at 3 blocks/SM
#define NCH     256      // 4 images * 64 filters
#define NTHR    256
#define EPS_BN  1e-5f

// Deterministic reduction scratch (no atomics -> bitwise-stable across replays)
__device__ float g_partial[2 * NCH][NBLK];   // [0,256)=sum, [256,512)=sumsq
__device__ float g_scale[NCH];
__device__ float g_shift[NCH];

// smem row order: 0=e0, 1=r0, 2=e1, 3=ht0, 4=tt0, 5=ht1, 6=tt1, 7=ht2, 8=tt2
__device__ __forceinline__ void load_rows(float* rows, const int* __restrict__ xr,
                                          const float* __restrict__ rel,
                                          const float* __restrict__ ent,
                                          const float* __restrict__ typ, int tid) {
    for (int i = tid; i < 9 * 32; i += NTHR) {
        int v  = i >> 5;
        int e4 = (i & 31) << 2;
        const float* src;
        int id;
        if (v == 0)      { src = ent; id = xr[1]; }
        else if (v == 1) { src = rel; id = xr[0]; }
        else if (v == 2) { src = ent; id = xr[3]; }
        else             { src = typ; id = xr[v + 1]; }   // rows 3..8 -> cols 4..9
        float4 val = *(const float4*)(src + (long)id * E_DIM + e4);
        *(float4*)(rows + v * E_DIM + e4) = val;
    }
}

// A[v]=row_v[x], Bw[v]=row_v[x+1], C[v]=row_v[x+2]
// o[0]=conv1 value; o[1..3]=conv2 arm values (shared rel0 mid-row computed once)
__device__ __forceinline__ void conv_vals(const float* A, const float* Bw, const float* C,
                                          const float* W1, const float* W2, float* o) {
    float c1;
    c1 = W1[0] * A[0];
    c1 = fmaf(W1[1], Bw[0], c1);
    c1 = fmaf(W1[2], C[0],  c1);
    c1 = fmaf(W1[3], A[1],  c1);
    c1 = fmaf(W1[4], Bw[1], c1);
    c1 = fmaf(W1[5], C[1],  c1);
    c1 = fmaf(W1[6], A[2],  c1);
    c1 = fmaf(W1[7], Bw[2], c1);
    c1 = fmaf(W1[8], C[2],  c1);
    o[0] = c1;

    float mid;                       // shared middle row (rel0) of all 3 arms
    mid = W2[3] * A[1];
    mid = fmaf(W2[4], Bw[1], mid);
    mid = fmaf(W2[5], C[1],  mid);

#pragma unroll
    for (int a = 0; a < 3; a++) {
        int ht = 3 + 2 * a, tt = 4 + 2 * a;
        float ca = mid;
        ca = fmaf(W2[0], A[ht],  ca);
        ca = fmaf(W2[1], Bw[ht], ca);
        ca = fmaf(W2[2], C[ht],  ca);
        ca = fmaf(W2[6], A[tt],  ca);
        ca = fmaf(W2[7], Bw[tt], ca);
        ca = fmaf(W2[8], C[tt],  ca);
        o[1 + a] = ca;
    }
}

// ---------------- Kernel 1: conv recompute + per-channel sum/sumsq partials ---
__global__ void __launch_bounds__(NTHR, 3)
k_stats(const int* __restrict__ xb,
        const float* __restrict__ rel, const float* __restrict__ ent,
        const float* __restrict__ typ,
        const float* __restrict__ c1w, const float* __restrict__ c2w) {
    __shared__ float rows[9 * E_DIM];
    __shared__ float red[NTHR][8];
    int tid = threadIdx.x;
    int f = tid & 63, g = tid >> 6;

    float W1[9], W2[9];
#pragma unroll
    for (int j = 0; j < 9; j++) { W1[j] = c1w[f * 9 + j]; W2[j] = c2w[f * 9 + j]; }

    float s[4] = {0.f, 0.f, 0.f, 0.f}, q[4] = {0.f, 0.f, 0.f, 0.f};

    int b0 = (int)(((long)blockIdx.x * B_TOT) / NBLK);
    int b1 = (int)(((long)(blockIdx.x + 1) * B_TOT) / NBLK);
    int x0 = g * 32, x1 = min(x0 + 32, W_DIM);

    for (int b = b0; b < b1; b++) {
        load_rows(rows, xb + b * 10, rel, ent, typ, tid);
        __syncthreads();

        float A[9], Bw[9];
#pragma unroll
        for (int v = 0; v < 9; v++) { A[v] = rows[v * E_DIM + x0]; Bw[v] = rows[v * E_DIM + x0 + 1]; }

#pragma unroll 3
        for (int x = x0; x < x1; x++) {
            float C[9];
#pragma unroll
            for (int v = 0; v < 9; v++) C[v] = rows[v * E_DIM + x + 2];
            float o[4];
            conv_vals(A, Bw, C, W1, W2, o);
#pragma unroll
            for (int k = 0; k < 4; k++) { s[k] += o[k]; q[k] = fmaf(o[k], o[k], q[k]); }
#pragma unroll
            for (int v = 0; v < 9; v++) { A[v] = Bw[v]; Bw[v] = C[v]; }
        }
        __syncthreads();
    }

#pragma unroll
    for (int k = 0; k < 4; k++) { red[tid][k] = s[k]; red[tid][4 + k] = q[k]; }
    __syncthreads();

    // write 512 channel partials (stat-major): c = stat*256 + img*64 + f
    for (int c = tid; c < 2 * NCH; c += NTHR) {
        int stat = c >> 8, img = (c >> 6) & 3, ff = c & 63;
        float v = 0.f;
#pragma unroll
        for (int gg = 0; gg < 4; gg++) v += red[gg * 64 + ff][stat * 4 + img];
        g_partial[c][blockIdx.x] = v;
    }
}

// ---------------- Kernel 2: finalize BN -> scale/shift per channel ------------
__global__ void __launch_bounds__(NTHR)
k_finalize(const float* __restrict__ g1, const float* __restrict__ b1p,
           const float* __restrict__ g2, const float* __restrict__ b2p) {
    __shared__ float ss[NTHR], qq[NTHR];
    int c = blockIdx.x;      // img*64 + f
    int t = threadIdx.x;
    float s = 0.f, q = 0.f;
    for (int i = t; i < NBLK; i += NTHR) { s += g_partial[c][i]; q += g_partial[NCH + c][i]; }
    ss[t] = s; qq[t] = q;
    __syncthreads();
    for (int o = NTHR / 2; o > 0; o >>= 1) {
        if (t < o) { ss[t] += ss[t + o]; qq[t] += qq[t + o]; }
        __syncthreads();
    }
    if (t == 0) {
        float N = (float)B_TOT * (float)W_DIM;
        float mean = ss[0] / N;
        float var  = qq[0] / N - mean * mean;
        int img = c >> 6, ff = c & 63;
        float ga = img ? g2[ff] : g1[ff];
        float be = img ? b2p[ff] : b1p[ff];
        float sc = ga * rsqrtf(var + EPS_BN);
        g_scale[c] = sc;
        g_shift[c] = be - mean * sc;
    }
}

// ---------------- Kernel 3: recompute + BN + relu + min + fused FC ------------
#define FCN_STRIDE 127                       // stride-127 padding: conflict-free LDS
#define SM_ROWS_OFF (128 * FCN_STRIDE)       // 16256 floats
#define SM_RED_OFF  (SM_ROWS_OFF + 9 * E_DIM)
#define SM3_FLOATS  (SM_RED_OFF + 8)
#define SM3_BYTES   (SM3_FLOATS * 4)

__global__ void __launch_bounds__(NTHR, 3)
k_main(const int* __restrict__ xb,
       const float* __restrict__ rel, const float* __restrict__ ent,
       const float* __restrict__ typ,
       const float* __restrict__ c1w, const float* __restrict__ c2w,
       const float* __restrict__ fw, const float* __restrict__ fbp,
       float* __restrict__ out) {
    extern __shared__ float sm[];
    float* fcn  = sm;                 // padded [128][127]
    float* rows = sm + SM_ROWS_OFF;   // [9][128]
    float* red  = sm + SM_RED_OFF;    // [8]
    int tid = threadIdx.x;

    // stage FC weights with stride-127 padding (row r = section*64 + f)
    for (int i = tid; i < 128 * W_DIM; i += NTHR) {
        int r = i / W_DIM;
        int xc = i - r * W_DIM;
        fcn[r * FCN_STRIDE + xc] = fw[i];
    }

    int f = tid & 63, g = tid >> 6;
    float W1[9], W2[9];
#pragma unroll
    for (int j = 0; j < 9; j++) { W1[j] = c1w[f * 9 + j]; W2[j] = c2w[f * 9 + j]; }
    float sc1 = g_scale[f], sh1 = g_shift[f];
    float sc2[3], sh2[3];
#pragma unroll
    for (int a = 0; a < 3; a++) { sc2[a] = g_scale[(a + 1) * 64 + f]; sh2[a] = g_shift[(a + 1) * 64 + f]; }
    float fb = fbp[0];

    int b0 = (int)(((long)blockIdx.x * B_TOT) / NBLK);
    int b1 = (int)(((long)(blockIdx.x + 1) * B_TOT) / NBLK);
    int x0 = g * 32, x1 = min(x0 + 32, W_DIM);

    const float* fw1 = fcn + f * FCN_STRIDE;          // h1 section weights
    const float* fw2 = fcn + (64 + f) * FCN_STRIDE;   // min section weights

    __syncthreads();   // fcn staged

    for (int b = b0; b < b1; b++) {
        load_rows(rows, xb + b * 10, rel, ent, typ, tid);
        __syncthreads();

        float acc = 0.f;
        float A[9], Bw[9];
#pragma unroll
        for (int v = 0; v < 9; v++) { A[v] = rows[v * E_DIM + x0]; Bw[v] = rows[v * E_DIM + x0 + 1]; }

#pragma unroll 3
        for (int x = x0; x < x1; x++) {
            float C[9];
#pragma unroll
            for (int v = 0; v < 9; v++) C[v] = rows[v * E_DIM + x + 2];
            float o[4];
            conv_vals(A, Bw, C, W1, W2, o);

            float v1 = fmaxf(fmaf(sc1, o[0], sh1), 0.f);
            float m0 = fmaxf(fmaf(sc2[0], o[1], sh2[0]), 0.f);
            float m1 = fmaxf(fmaf(sc2[1], o[2], sh2[1]), 0.f);
            float m2 = fmaxf(fmaf(sc2[2], o[3], sh2[2]), 0.f);
            float mn = fminf(m0, fminf(m1, m2));

            acc = fmaf(v1, fw1[x], acc);
            acc = fmaf(mn, fw2[x], acc);
#pragma unroll
            for (int v = 0; v < 9; v++) { A[v] = Bw[v]; Bw[v] = C[v]; }
        }

        // block-reduce 256 partials -> out[b]
#pragma unroll
        for (int o2 = 16; o2; o2 >>= 1) acc += __shfl_xor_sync(0xffffffffu, acc, o2);
        __syncthreads();                 // all rows/red reads from prior phase done
        if ((tid & 31) == 0) red[tid >> 5] = acc;
        __syncthreads();
        if (tid == 0) {
            float t2 = 0.f;
#pragma unroll
            for (int w = 0; w < 8; w++) t2 += red[w];
            out[b] = t2 + fb;
        }
    }
}

extern "C" void kernel_launch(void* const* d_in, const int* in_sizes, int n_in,
                              void* d_out, int out_size) {
    // Input order per metadata: x_batch, [arity, mode], emb_relations, emb_entities,
    // emb_types, conv1_w, conv1_b, bn1_gamma, bn1_beta, conv2_w, conv2_b,
    // bn2_gamma, bn2_beta, fcn_w, fcn_b.
    // Detect whether the python-int scalars (arity, mode) materialized as inputs.
    int off = (n_in >= 16 && in_sizes[1] == 1) ? 2 : 0;

    const int*   xb  = (const int*)d_in[0];
    const float* rel = (const float*)d_in[1 + off];
    const float* ent = (const float*)d_in[2 + off];
    const float* typ = (const float*)d_in[3 + off];
    const float* c1w = (const float*)d_in[4 + off];
    // conv1_b (5+off) cancels under BN
    const float* g1  = (const float*)d_in[6 + off];
    const float* b1  = (const float*)d_in[7 + off];
    const float* c2w = (const float*)d_in[8 + off];
    // conv2_b (9+off) cancels under BN
    const float* g2  = (const float*)d_in[10 + off];
    const float* b2  = (const float*)d_in[11 + off];
    const float* fwp = (const float*)d_in[12 + off];
    const float* fbp = (const float*)d_in[13 + off];
    float* out = (float*)d_out;

    static bool attr_done = false;
    if (!attr_done) {
        cudaFuncSetAttribute(k_main, cudaFuncAttributeMaxDynamicSharedMemorySize, SM3_BYTES);
        attr_done = true;
    }

    k_stats<<<NBLK, NTHR>>>(xb, rel, ent, typ, c1w, c2w);
    k_finalize<<<NCH, NTHR>>>(g1, b1, g2, b2);
    k_main<<<NBLK, NTHR, SM3_BYTES>>>(xb, rel, ent, typ, c1w, c2w, fwp, fbp, out);
}

// round 3
// speedup vs baseline: 1.2485x; 1.2485x over previous
#include <cuda_runtime.h>

#define B_TOT 4096
#define E_DIM 128
#define W_DIM 126
#define NBLK  296        // 2 blocks/SM * 148 SMs -> one full wave
#define NCH   256
#define NTHR  256
#define EPS_BN 1e-5f

typedef unsigned long long u64;

// Deterministic reduction scratch (no atomics -> bitwise-stable across replays)
__device__ float g_partial[2 * NCH][NBLK];
__device__ float g_scale[NCH];
__device__ float g_shift[NCH];

// ---------- packed f32x2 helpers ----------
__device__ __forceinline__ u64 pk2(float a, float b) {
    u64 r; asm("mov.b64 %0,{%1,%2};" : "=l"(r) : "f"(a), "f"(b)); return r;
}
__device__ __forceinline__ void up2(u64 v, float& a, float& b) {
    asm("mov.b64 {%0,%1},%2;" : "=f"(a), "=f"(b) : "l"(v));
}
__device__ __forceinline__ u64 mul2(u64 a, u64 b) {
    u64 d; asm("mul.rn.f32x2 %0,%1,%2;" : "=l"(d) : "l"(a), "l"(b)); return d;
}
__device__ __forceinline__ u64 fma2(u64 a, u64 b, u64 c) {
    u64 d; asm("fma.rn.f32x2 %0,%1,%2,%3;" : "=l"(d) : "l"(a), "l"(b), "l"(c)); return d;
}
__device__ __forceinline__ u64 add2(u64 a, u64 b) {
    u64 d; asm("add.rn.f32x2 %0,%1,%2;" : "=l"(d) : "l"(a), "l"(b)); return d;
}

// ---------- gather staging (double-buffered) ----------
// smem row order: 0=e0, 1=r0, 2=e1, 3=ht0, 4=tt0, 5=ht1, 6=tt1, 7=ht2, 8=tt2
__device__ __forceinline__ float4 gath1(const int* __restrict__ xr, int i,
                                        const float* __restrict__ rel,
                                        const float* __restrict__ ent,
                                        const float* __restrict__ typ) {
    int v = i >> 5, e4 = (i & 31) << 2;
    const float* src; int col;
    if (v == 0)      { src = ent; col = 1; }
    else if (v == 1) { src = rel; col = 0; }
    else if (v == 2) { src = ent; col = 3; }
    else             { src = typ; col = v + 1; }   // rows 3..8 -> x cols 4..9
    int id = __ldg(xr + col);
    return *(const float4*)(src + (long)id * E_DIM + e4);
}

// Al[x] = row[x]; Sh[x] = row[x+1]  (shifted copy -> all packed pairs aligned)
__device__ __forceinline__ void put1(float* Al, float* Sh, int i, float4 val) {
    int v = i >> 5, e4 = (i & 31) << 2;
    *(float4*)(Al + v * E_DIM + e4) = val;
    float* s = Sh + v * E_DIM + e4;
    *(float2*)s = make_float2(val.y, val.z);
    s[2] = val.w;
    if (e4) s[-1] = val.x;
}

__device__ __forceinline__ void build_wp(const float* __restrict__ c1w,
                                         const float* __restrict__ c2w,
                                         int f, u64* W1, u64* W2) {
#pragma unroll
    for (int j = 0; j < 9; j++) {
        float w1 = c1w[f * 9 + j], w2 = c2w[f * 9 + j];
        W1[j] = pk2(w1, w1); W2[j] = pk2(w2, w2);
    }
}

__device__ __forceinline__ void fetch4(const float* Al, const float* Sh, int v, int x,
                                       u64& P0, u64& P1, u64& P2, u64& P3, u64& P4) {
    float4 q = *(const float4*)(Al + v * E_DIM + x);
    float4 s = *(const float4*)(Sh + v * E_DIM + x);
    P0 = pk2(q.x, q.y); P1 = pk2(s.x, s.y);
    P2 = pk2(q.z, q.w); P3 = pk2(s.z, s.w);
    P4 = *(const u64*)(Al + v * E_DIM + x + 4);
}

// 4 outputs (x..x+3) for all 4 images; o[2k],o[2k+1] = img k pairs (A,B)
__device__ __forceinline__ void conv4(const float* Al, const float* Sh, int x,
                                      const u64* W1, const u64* W2, u64* o) {
    u64 P0, P1, P2, P3, P4, c1A, c1B, mA, mB;
    fetch4(Al, Sh, 0, x, P0, P1, P2, P3, P4);
    c1A = mul2(W1[0], P0); c1A = fma2(W1[1], P1, c1A); c1A = fma2(W1[2], P2, c1A);
    c1B = mul2(W1[0], P2); c1B = fma2(W1[1], P3, c1B); c1B = fma2(W1[2], P4, c1B);
    fetch4(Al, Sh, 1, x, P0, P1, P2, P3, P4);
    c1A = fma2(W1[3], P0, c1A); c1A = fma2(W1[4], P1, c1A); c1A = fma2(W1[5], P2, c1A);
    c1B = fma2(W1[3], P2, c1B); c1B = fma2(W1[4], P3, c1B); c1B = fma2(W1[5], P4, c1B);
    mA  = mul2(W2[3], P0); mA = fma2(W2[4], P1, mA); mA = fma2(W2[5], P2, mA);
    mB  = mul2(W2[3], P2); mB = fma2(W2[4], P3, mB); mB = fma2(W2[5], P4, mB);
    fetch4(Al, Sh, 2, x, P0, P1, P2, P3, P4);
    c1A = fma2(W1[6], P0, c1A); c1A = fma2(W1[7], P1, c1A); c1A = fma2(W1[8], P2, c1A);
    c1B = fma2(W1[6], P2, c1B); c1B = fma2(W1[7], P3, c1B); c1B = fma2(W1[8], P4, c1B);
    o[0] = c1A; o[1] = c1B;
#pragma unroll
    for (int a = 0; a < 3; a++) {
        u64 tA, tB;
        fetch4(Al, Sh, 3 + 2 * a, x, P0, P1, P2, P3, P4);
        tA = fma2(W2[0], P0, mA); tA = fma2(W2[1], P1, tA); tA = fma2(W2[2], P2, tA);
        tB = fma2(W2[0], P2, mB); tB = fma2(W2[1], P3, tB); tB = fma2(W2[2], P4, tB);
        fetch4(Al, Sh, 4 + 2 * a, x, P0, P1, P2, P3, P4);
        tA = fma2(W2[6], P0, tA); tA = fma2(W2[7], P1, tA); tA = fma2(W2[8], P2, tA);
        tB = fma2(W2[6], P2, tB); tB = fma2(W2[7], P3, tB); tB = fma2(W2[8], P4, tB);
        o[2 + 2 * a] = tA; o[3 + 2 * a] = tB;
    }
}

// tail: 2 outputs (x,x+1); o[k] = img k pair
__device__ __forceinline__ void conv2t(const float* Al, const float* Sh, int x,
                                       const u64* W1, const u64* W2, u64* o) {
    u64 P0, P1, P2, c, m;
#define FETCH2(v) P0 = *(const u64*)(Al + (v)*E_DIM + x); \
                  P1 = *(const u64*)(Sh + (v)*E_DIM + x); \
                  P2 = *(const u64*)(Al + (v)*E_DIM + x + 2);
    FETCH2(0)
    c = mul2(W1[0], P0); c = fma2(W1[1], P1, c); c = fma2(W1[2], P2, c);
    FETCH2(1)
    c = fma2(W1[3], P0, c); c = fma2(W1[4], P1, c); c = fma2(W1[5], P2, c);
    m = mul2(W2[3], P0); m = fma2(W2[4], P1, m); m = fma2(W2[5], P2, m);
    FETCH2(2)
    c = fma2(W1[6], P0, c); c = fma2(W1[7], P1, c); c = fma2(W1[8], P2, c);
    o[0] = c;
#pragma unroll
    for (int a = 0; a < 3; a++) {
        u64 t;
        FETCH2(3 + 2 * a)
        t = fma2(W2[0], P0, m); t = fma2(W2[1], P1, t); t = fma2(W2[2], P2, t);
        FETCH2(4 + 2 * a)
        t = fma2(W2[6], P0, t); t = fma2(W2[7], P1, t); t = fma2(W2[8], P2, t);
        o[1 + a] = t;
    }
#undef FETCH2
}

// ---------------- Kernel 1: conv recompute + per-channel sum/sumsq partials ---
__global__ void __launch_bounds__(NTHR, 2)
k_stats(const int* __restrict__ xb,
        const float* __restrict__ rel, const float* __restrict__ ent,
        const float* __restrict__ typ,
        const float* __restrict__ c1w, const float* __restrict__ c2w) {
    __shared__ float rowsA[2][9 * E_DIM];
    __shared__ float rowsS[2][9 * E_DIM];
    __shared__ float red[NTHR][8];
    int tid = threadIdx.x, f = tid & 63, g = tid >> 6;

    u64 W1[9], W2[9];
    build_wp(c1w, c2w, f, W1, W2);

    u64 S[4], Q[4];
#pragma unroll
    for (int k = 0; k < 4; k++) { S[k] = pk2(0.f, 0.f); Q[k] = pk2(0.f, 0.f); }

    int b0 = (int)(((long)blockIdx.x * B_TOT) / NBLK);
    int b1 = (int)(((long)(blockIdx.x + 1) * B_TOT) / NBLK);
    int x0 = g * 32, x1 = min(x0 + 32, W_DIM);
    bool two = tid < 32;

    float4 sa = gath1(xb + b0 * 10, tid, rel, ent, typ);
    float4 sb = make_float4(0.f, 0.f, 0.f, 0.f);
    if (two) sb = gath1(xb + b0 * 10, tid + 256, rel, ent, typ);

    for (int b = b0; b < b1; b++) {
        int cur = (b - b0) & 1;
        put1(rowsA[cur], rowsS[cur], tid, sa);
        if (two) put1(rowsA[cur], rowsS[cur], tid + 256, sb);
        __syncthreads();
        if (b + 1 < b1) {
            sa = gath1(xb + (b + 1) * 10, tid, rel, ent, typ);
            if (two) sb = gath1(xb + (b + 1) * 10, tid + 256, rel, ent, typ);
        }
        const float* Al = rowsA[cur];
        const float* Sh = rowsS[cur];
        int x = x0;
        for (; x + 4 <= x1; x += 4) {
            u64 o[8];
            conv4(Al, Sh, x, W1, W2, o);
#pragma unroll
            for (int k = 0; k < 4; k++) {
                S[k] = add2(S[k], o[2 * k]);  S[k] = add2(S[k], o[2 * k + 1]);
                Q[k] = fma2(o[2 * k], o[2 * k], Q[k]);
                Q[k] = fma2(o[2 * k + 1], o[2 * k + 1], Q[k]);
            }
        }
        if (x < x1) {
            u64 o[4];
            conv2t(Al, Sh, x, W1, W2, o);
#pragma unroll
            for (int k = 0; k < 4; k++) {
                S[k] = add2(S[k], o[k]);
                Q[k] = fma2(o[k], o[k], Q[k]);
            }
        }
    }

#pragma unroll
    for (int k = 0; k < 4; k++) {
        float a, b2;
        up2(S[k], a, b2); red[tid][k] = a + b2;
        up2(Q[k], a, b2); red[tid][4 + k] = a + b2;
    }
    __syncthreads();

    // 512 channel partials (stat-major): c = stat*256 + img*64 + f
    for (int c = tid; c < 2 * NCH; c += NTHR) {
        int stat = c >> 8, img = (c >> 6) & 3, ff = c & 63;
        float v = 0.f;
#pragma unroll
        for (int gg = 0; gg < 4; gg++) v += red[gg * 64 + ff][stat * 4 + img];
        g_partial[c][blockIdx.x] = v;
    }
}

// ---------------- Kernel 2: finalize BN -> scale/shift per channel ------------
__global__ void __launch_bounds__(NTHR)
k_finalize(const float* __restrict__ g1, const float* __restrict__ b1p,
           const float* __restrict__ g2, const float* __restrict__ b2p) {
    __shared__ float ss[NTHR], qq[NTHR];
    int c = blockIdx.x;      // img*64 + f
    int t = threadIdx.x;
    float s = 0.f, q = 0.f;
    for (int i = t; i < NBLK; i += NTHR) { s += g_partial[c][i]; q += g_partial[NCH + c][i]; }
    ss[t] = s; qq[t] = q;
    __syncthreads();
    for (int o = NTHR / 2; o > 0; o >>= 1) {
        if (t < o) { ss[t] += ss[t + o]; qq[t] += qq[t + o]; }
        __syncthreads();
    }
    if (t == 0) {
        float N = (float)B_TOT * (float)W_DIM;
        float mean = ss[0] / N;
        float var  = qq[0] / N - mean * mean;
        int img = c >> 6, ff = c & 63;
        float ga = img ? g2[ff] : g1[ff];
        float be = img ? b2p[ff] : b1p[ff];
        float sc = ga * rsqrtf(var + EPS_BN);
        g_scale[c] = sc;
        g_shift[c] = be - mean * sc;
    }
}

// ---------------- Kernel 3: recompute + BN + relu + min + fused FC ------------
#define FCN_STRIDE 132                       // 4f*132 words: conflict-free LDS.128
#define SM_AL_OFF  (128 * FCN_STRIDE)        // 16896 floats
#define SM_SH_OFF  (SM_AL_OFF + 2 * 9 * E_DIM)
#define SM_RED_OFF (SM_SH_OFF + 2 * 9 * E_DIM)
#define SM3_FLOATS (SM_RED_OFF + 16)
#define SM3_BYTES  (SM3_FLOATS * 4)

__global__ void __launch_bounds__(NTHR, 2)
k_main(const int* __restrict__ xb,
       const float* __restrict__ rel, const float* __restrict__ ent,
       const float* __restrict__ typ,
       const float* __restrict__ c1w, const float* __restrict__ c2w,
       const float* __restrict__ fw, const float* __restrict__ fbp,
       float* __restrict__ out) {
    extern __shared__ float sm[];
    float* fcn  = sm;                          // padded [128][132]
    float* redm = sm + SM_RED_OFF;             // [2][8]
    int tid = threadIdx.x, f = tid & 63, g = tid >> 6;

    for (int i = tid; i < 128 * W_DIM; i += NTHR) {
        int r = i / W_DIM, xc = i - r * W_DIM;
        fcn[r * FCN_STRIDE + xc] = fw[i];
    }

    u64 W1[9], W2[9];
    build_wp(c1w, c2w, f, W1, W2);
    float t1 = g_scale[f], t2 = g_shift[f];
    u64 sc1p = pk2(t1, t1), sh1p = pk2(t2, t2);
    u64 sc2p[3], sh2p[3];
#pragma unroll
    for (int a = 0; a < 3; a++) {
        float sa2 = g_scale[(a + 1) * 64 + f], sb2 = g_shift[(a + 1) * 64 + f];
        sc2p[a] = pk2(sa2, sa2); sh2p[a] = pk2(sb2, sb2);
    }
    float fb = fbp[0];

    int b0 = (int)(((long)blockIdx.x * B_TOT) / NBLK);
    int b1 = (int)(((long)(blockIdx.x + 1) * B_TOT) / NBLK);
    int x0 = g * 32, x1 = min(x0 + 32, W_DIM);
    bool two = tid < 32;
    const float* fw1 = fcn + f * FCN_STRIDE;
    const float* fw2 = fcn + (64 + f) * FCN_STRIDE;

    float4 sa = gath1(xb + b0 * 10, tid, rel, ent, typ);
    float4 sb = make_float4(0.f, 0.f, 0.f, 0.f);
    if (two) sb = gath1(xb + b0 * 10, tid + 256, rel, ent, typ);

    for (int b = b0; b < b1; b++) {
        int cur = (b - b0) & 1;
        put1(sm + SM_AL_OFF + cur * 9 * E_DIM, sm + SM_SH_OFF + cur * 9 * E_DIM, tid, sa);
        if (two) put1(sm + SM_AL_OFF + cur * 9 * E_DIM, sm + SM_SH_OFF + cur * 9 * E_DIM, tid + 256, sb);
        __syncthreads();                   // staging done; prev redm visible
        if (b > b0 && tid == 0) {
            float t = 0.f;
#pragma unroll
            for (int w = 0; w < 8; w++) t += redm[(cur ^ 1) * 8 + w];
            out[b - 1] = t + fb;
        }
        if (b + 1 < b1) {
            sa = gath1(xb + (b + 1) * 10, tid, rel, ent, typ);
            if (two) sb = gath1(xb + (b + 1) * 10, tid + 256, rel, ent, typ);
        }
        const float* Al = sm + SM_AL_OFF + cur * 9 * E_DIM;
        const float* Sh = sm + SM_SH_OFF + cur * 9 * E_DIM;

        u64 accp = pk2(0.f, 0.f);
        int x = x0;
        for (; x + 4 <= x1; x += 4) {
            u64 o[8];
            conv4(Al, Sh, x, W1, W2, o);
            float v0, v1, v2, v3;
            { u64 hA = fma2(sc1p, o[0], sh1p), hB = fma2(sc1p, o[1], sh1p);
              up2(hA, v0, v1); up2(hB, v2, v3); }
            v0 = fmaxf(v0, 0.f); v1 = fmaxf(v1, 0.f); v2 = fmaxf(v2, 0.f); v3 = fmaxf(v3, 0.f);
            float mn0, mn1, mn2, mn3;
            { u64 hA = fma2(sc2p[0], o[2], sh2p[0]), hB = fma2(sc2p[0], o[3], sh2p[0]);
              up2(hA, mn0, mn1); up2(hB, mn2, mn3);
              mn0 = fmaxf(mn0, 0.f); mn1 = fmaxf(mn1, 0.f); mn2 = fmaxf(mn2, 0.f); mn3 = fmaxf(mn3, 0.f); }
#pragma unroll
            for (int a = 1; a < 3; a++) {
                float u0, u1, u2, u3;
                u64 hA = fma2(sc2p[a], o[2 + 2 * a], sh2p[a]), hB = fma2(sc2p[a], o[3 + 2 * a], sh2p[a]);
                up2(hA, u0, u1); up2(hB, u2, u3);
                mn0 = fminf(mn0, fmaxf(u0, 0.f)); mn1 = fminf(mn1, fmaxf(u1, 0.f));
                mn2 = fminf(mn2, fmaxf(u2, 0.f)); mn3 = fminf(mn3, fmaxf(u3, 0.f));
            }
            float4 w1q = *(const float4*)(fw1 + x);
            float4 w2q = *(const float4*)(fw2 + x);
            accp = fma2(pk2(v0, v1), pk2(w1q.x, w1q.y), accp);
            accp = fma2(pk2(v2, v3), pk2(w1q.z, w1q.w), accp);
            accp = fma2(pk2(mn0, mn1), pk2(w2q.x, w2q.y), accp);
            accp = fma2(pk2(mn2, mn3), pk2(w2q.z, w2q.w), accp);
        }
        if (x < x1) {          // tail pair (only g==3)
            u64 o[4];
            conv2t(Al, Sh, x, W1, W2, o);
            float v0, v1;
            { u64 h = fma2(sc1p, o[0], sh1p); up2(h, v0, v1); }
            v0 = fmaxf(v0, 0.f); v1 = fmaxf(v1, 0.f);
            float mn0, mn1;
            { u64 h = fma2(sc2p[0], o[1], sh2p[0]); up2(h, mn0, mn1);
              mn0 = fmaxf(mn0, 0.f); mn1 = fmaxf(mn1, 0.f); }
#pragma unroll
            for (int a = 1; a < 3; a++) {
                float u0, u1;
                u64 h = fma2(sc2p[a], o[1 + a], sh2p[a]); up2(h, u0, u1);
                mn0 = fminf(mn0, fmaxf(u0, 0.f)); mn1 = fminf(mn1, fmaxf(u1, 0.f));
            }
            accp = fma2(pk2(v0, v1), *(const u64*)(fw1 + x), accp);
            accp = fma2(pk2(mn0, mn1), *(const u64*)(fw2 + x), accp);
        }

        float aa, bb;
        up2(accp, aa, bb);
        float acc = aa + bb;
#pragma unroll
        for (int o2 = 16; o2; o2 >>= 1) acc += __shfl_xor_sync(0xffffffffu, acc, o2);
        if ((tid & 31) == 0) redm[cur * 8 + (tid >> 5)] = acc;
    }
    __syncthreads();
    if (tid == 0) {
        int lc = (b1 - 1 - b0) & 1;
        float t = 0.f;
#pragma unroll
        for (int w = 0; w < 8; w++) t += redm[lc * 8 + w];
        out[b1 - 1] = t + fb;
    }
}

extern "C" void kernel_launch(void* const* d_in, const int* in_sizes, int n_in,
                              void* d_out, int out_size) {
    int off = (n_in >= 16 && in_sizes[1] == 1) ? 2 : 0;

    const int*   xb  = (const int*)d_in[0];
    const float* rel = (const float*)d_in[1 + off];
    const float* ent = (const float*)d_in[2 + off];
    const float* typ = (const float*)d_in[3 + off];
    const float* c1w = (const float*)d_in[4 + off];
    const float* g1  = (const float*)d_in[6 + off];
    const float* b1  = (const float*)d_in[7 + off];
    const float* c2w = (const float*)d_in[8 + off];
    const float* g2  = (const float*)d_in[10 + off];
    const float* b2  = (const float*)d_in[11 + off];
    const float* fwp = (const float*)d_in[12 + off];
    const float* fbp = (const float*)d_in[13 + off];
    float* out = (float*)d_out;

    static bool attr_done = false;
    if (!attr_done) {
        cudaFuncSetAttribute(k_main, cudaFuncAttributeMaxDynamicSharedMemorySize, SM3_BYTES);
        attr_done = true;
    }

    k_stats<<<NBLK, NTHR>>>(xb, rel, ent, typ, c1w, c2w);
    k_finalize<<<NCH, NTHR>>>(g1, b1, g2, b2);
    k_main<<<NBLK, NTHR, SM3_BYTES>>>(xb, rel, ent, typ, c1w, c2w, fwp, fbp, out);
}